// round 13
// baseline (speedup 1.0000x reference)
#include <cuda_runtime.h>

// Problem constants (fixed shapes from reference)
#define TOK   (4 * 4096)   // B*S = 16384 tokens
#define HDIM  2048
#define TAU   3e-3f        // tier-1 argmax-gap threshold (tf32 fast pass)
#define RTB   4            // tokens batched per recheck block
#define RQ    8            // recheck jcol split factor

// Scratch
__device__ float g_bufA[(size_t)TOK * 1024];  // branch1 stage-2
__device__ float g_bufB[(size_t)TOK * 1024];  // branch1 stage-1
__device__ float g_bufC[(size_t)TOK * 512];   // branch2 stage-1
__device__ float g_bufD[(size_t)TOK * 512];   // branch2 stage-2
__device__ float g_psel[TOK][4][3];           // fused tier-1 logit partials
__device__ float g_rpart[TOK][RQ][3];         // recheck partial logits
__device__ int   g_idx1[TOK];
__device__ int   g_idx2[TOK];
__device__ int   g_idxR[TOK];
__device__ int   g_rIdx[TOK];                 // per-token recheck slot (-1 = none)
__device__ int   g_sel[TOK];
__device__ int   g_cnt[3];   // [0]=branch1, [1]=branch2, [2]=recheck

// ---------------------------------------------------------------------------
// out = h (default for selected==0; branch scatters overwrite). Also zeroes
// the counters (block 0) so no separate init launch is needed.
__global__ void k_prep(const float* __restrict__ h, float* __restrict__ out) {
    if (blockIdx.x == 0 && threadIdx.x < 3) g_cnt[threadIdx.x] = 0;
    int i = blockIdx.x * blockDim.x + threadIdx.x;     // float4 index
    if (i < TOK * (HDIM / 4))
        ((float4*)out)[i] = ((const float4*)h)[i];
}

// ---------------------------------------------------------------------------
// Tier-1 decision from fused selector partials (fixed combine order).
// Near-ties (gap < TAU) get a recheck slot recorded in g_rIdx.
__global__ void k_seldec(const float* __restrict__ b2) {
    int tok = blockIdx.x * blockDim.x + threadIdx.x;
    if (tok >= TOK) return;
    float s0 = b2[0], s1 = b2[1], s2 = b2[2];
    #pragma unroll
    for (int q = 0; q < 4; q++) {
        s0 += g_psel[tok][q][0];
        s1 += g_psel[tok][q][1];
        s2 += g_psel[tok][q][2];
    }
    int sel = 0; float best = s0;             // first-max rule: strict '>'
    if (s1 > best) { best = s1; sel = 1; }
    if (s2 > best) { best = s2; sel = 2; }
    g_sel[tok] = sel;
    float m1 = fmaxf(s0, fmaxf(s1, s2));
    float mn = fminf(s0, fminf(s1, s2));
    float m2 = s0 + s1 + s2 - m1 - mn;        // second largest
    int flag = -1;
    if (m1 - m2 < TAU) {
        int p = atomicAdd(&g_cnt[2], 1);
        g_idxR[p] = tok;
        flag = p;
    }
    g_rIdx[tok] = flag;
}

// Tier-2: exact fp32 recompute, RTB tokens per block, jcols split RQ ways
// across blockIdx.y. Coalesced W1 loads; fixed-order reduces throughout.
__global__ __launch_bounds__(256)
void k_sel_exact(const float* __restrict__ h,
                 const float* __restrict__ freq,
                 const float* __restrict__ imp,
                 const float* __restrict__ W1,   // [512,2048]
                 const float* __restrict__ b1,
                 const float* __restrict__ W2)   // [3,512]
{
    __shared__ float xs[RTB][HDIM];          // 32 KB
    __shared__ float wp[8][RTB][3];          // per-warp logit partials
    const int tid  = threadIdx.x;
    const int lane = tid & 31;
    const int warp = tid >> 5;
    const int qy   = blockIdx.y;             // jcol slice 0..RQ-1
    const int nR = g_cnt[2];
    for (int base = blockIdx.x * RTB; base < nR; base += gridDim.x * RTB) {
        const int nt = min(RTB, nR - base);
        __syncthreads();                     // protect xs/wp reuse across iters
        for (int t = 0; t < nt; t++) {
            int tok = g_idxR[base + t];
            float fr = freq[tok], im = imp[tok];
            for (int k = tid; k < HDIM; k += 256) {
                float s = (k < HDIM / 2) ? fr : im;
                xs[t][k] = h[(size_t)tok * HDIM + k] * s;
            }
        }
        for (int t = nt; t < RTB; t++)
            for (int k = tid; k < HDIM; k += 256) xs[t][k] = 0.f;
        __syncthreads();

        float p[RTB][3];
        #pragma unroll
        for (int t = 0; t < RTB; t++)
            p[t][0] = p[t][1] = p[t][2] = 0.f;

        // this block: jcols [qy*64, qy*64+64); warp handles 8, 4 at a time
        #pragma unroll
        for (int grp = 0; grp < 2; grp++) {
            const int jcol0 = qy * 64 + warp * 8 + grp * 4;
            const float4* w0 = (const float4*)(W1 + (size_t)(jcol0 + 0) * HDIM);
            const float4* w1 = (const float4*)(W1 + (size_t)(jcol0 + 1) * HDIM);
            const float4* w2 = (const float4*)(W1 + (size_t)(jcol0 + 2) * HDIM);
            const float4* w3 = (const float4*)(W1 + (size_t)(jcol0 + 3) * HDIM);
            float acc[4][RTB];
            #pragma unroll
            for (int jj = 0; jj < 4; jj++)
                #pragma unroll
                for (int t = 0; t < RTB; t++) acc[jj][t] = 0.f;

            #pragma unroll 2
            for (int q = 0; q < 16; q++) {
                const int k4 = lane + q * 32;          // coalesced
                float4 wv[4] = {w0[k4], w1[k4], w2[k4], w3[k4]};
                float4 xv[RTB];
                #pragma unroll
                for (int t = 0; t < RTB; t++)
                    xv[t] = ((const float4*)xs[t])[k4];
                #pragma unroll
                for (int jj = 0; jj < 4; jj++)
                    #pragma unroll
                    for (int t = 0; t < RTB; t++)
                        acc[jj][t] = fmaf(wv[jj].x, xv[t].x,
                                     fmaf(wv[jj].y, xv[t].y,
                                     fmaf(wv[jj].z, xv[t].z,
                                     fmaf(wv[jj].w, xv[t].w, acc[jj][t]))));
            }
            // fixed shfl tree reduce
            #pragma unroll
            for (int o = 16; o; o >>= 1)
                #pragma unroll
                for (int jj = 0; jj < 4; jj++)
                    #pragma unroll
                    for (int t = 0; t < RTB; t++)
                        acc[jj][t] += __shfl_down_sync(0xffffffffu, acc[jj][t], o);
            if (lane == 0) {
                #pragma unroll
                for (int jj = 0; jj < 4; jj++) {
                    const int jcol = jcol0 + jj;
                    float bb  = b1[jcol];
                    float w20 = W2[jcol], w21 = W2[512 + jcol], w22 = W2[1024 + jcol];
                    #pragma unroll
                    for (int t = 0; t < RTB; t++) {
                        float hj = fmaxf(acc[jj][t] + bb, 0.f);
                        p[t][0] = fmaf(hj, w20, p[t][0]);
                        p[t][1] = fmaf(hj, w21, p[t][1]);
                        p[t][2] = fmaf(hj, w22, p[t][2]);
                    }
                }
            }
        }

        if (lane == 0)
            #pragma unroll
            for (int t = 0; t < RTB; t++) {
                wp[warp][t][0] = p[t][0];
                wp[warp][t][1] = p[t][1];
                wp[warp][t][2] = p[t][2];
            }
        __syncthreads();
        if (tid < nt) {
            float s0 = 0.f, s1 = 0.f, s2 = 0.f;
            #pragma unroll
            for (int w = 0; w < 8; w++) {
                s0 += wp[w][tid][0];
                s1 += wp[w][tid][1];
                s2 += wp[w][tid][2];
            }
            g_rpart[base + tid][qy][0] = s0;
            g_rpart[base + tid][qy][1] = s1;
            g_rpart[base + tid][qy][2] = s2;
        }
    }
}

// Build branch index lists. Rechecked tokens combine their RQ partials in
// fixed order (exact fp32 decision); others use the tier-1 decision.
__global__ void k_compact(const float* __restrict__ b2) {
    int tok = blockIdx.x * blockDim.x + threadIdx.x;
    if (tok >= TOK) return;
    int r = g_rIdx[tok];
    int sel;
    if (r >= 0) {
        float s0 = b2[0], s1 = b2[1], s2 = b2[2];
        #pragma unroll
        for (int q = 0; q < RQ; q++) {
            s0 += g_rpart[r][q][0];
            s1 += g_rpart[r][q][1];
            s2 += g_rpart[r][q][2];
        }
        sel = 0; float best = s0;
        if (s1 > best) { best = s1; sel = 1; }
        if (s2 > best) { best = s2; sel = 2; }
    } else {
        sel = g_sel[tok];
    }
    if (sel == 1)      { int p = atomicAdd(&g_cnt[0], 1); g_idx1[p] = tok; }
    else if (sel == 2) { int p = atomicAdd(&g_cnt[1], 1); g_idx2[p] = tok; }
}

// ---------------------------------------------------------------------------
// tf32 tensor-core GEMM machinery (mma.m16n8k8, cp.async 3-stage, XOR swizzle)
// ---------------------------------------------------------------------------
__device__ __forceinline__ void mma_tf32(float (&d)[4], const unsigned (&a)[4],
                                         const unsigned (&b)[2]) {
    asm volatile(
        "mma.sync.aligned.m16n8k8.row.col.f32.tf32.tf32.f32 "
        "{%0,%1,%2,%3}, {%4,%5,%6,%7}, {%8,%9}, {%0,%1,%2,%3};\n"
        : "+f"(d[0]), "+f"(d[1]), "+f"(d[2]), "+f"(d[3])
        : "r"(a[0]), "r"(a[1]), "r"(a[2]), "r"(a[3]), "r"(b[0]), "r"(b[1]));
}

__device__ __forceinline__ void cp16(unsigned dst, const void* src, int nbytes) {
    asm volatile("cp.async.cg.shared.global [%0], [%1], 16, %2;"
                 :: "r"(dst), "l"(src), "r"(nbytes));
}

#define BK   32
#define ASZ  (128 * BK)                    // words per A-matrix per stage
#define STGW (2 * ASZ)                     // words per stage (selector tile)
#define STGB (STGW * 4)
#define TC_SMEM (3 * STGB)                 // 96 KB (selector kernel)

// ---------------------------------------------------------------------------
// Selector GEMM: 128x128 tile, MOD modulation + fused logit-partial epilogue.
// ---------------------------------------------------------------------------
__global__ __launch_bounds__(256, 2)
void k_gemm_sel(const float* __restrict__ A, const float* __restrict__ W,
                const float* __restrict__ bias,
                const float* __restrict__ freq, const float* __restrict__ imp,
                const float* __restrict__ W2sel)
{
    extern __shared__ float sm[];
    const int tileM = blockIdx.y * 128;
    const int tileN = blockIdx.x * 128;
    const int K = HDIM;

    const int tid  = threadIdx.x;
    const int lane = tid & 31;
    const int warp = tid >> 5;
    const int wm0 = (warp >> 2) * 64;
    const int wn0 = (warp & 3) * 32;
    const int g = lane >> 2;
    const int c = lane & 3;

    const int j  = tid & 7;
    const int r0 = tid >> 3;
    const float* asrc[4];
    const float* bsrc[4];
    unsigned adst[4], bdst[4];
    const unsigned smb = (unsigned)__cvta_generic_to_shared(sm);
    #pragma unroll
    for (int i = 0; i < 4; i++) {
        int r = r0 + 32 * i;
        asrc[i] = A + (size_t)(tileM + r) * K + j * 4;
        bsrc[i] = W + (size_t)(tileN + r) * K + j * 4;
        unsigned woff = r * BK + ((j ^ (r & 7)) << 2);
        adst[i] = smb + woff * 4;
        bdst[i] = smb + (ASZ + woff) * 4;
    }

    float sfr[4][2], sim[4][2];
    #pragma unroll
    for (int mt = 0; mt < 4; mt++) {
        int rA = tileM + wm0 + mt * 16 + g;
        int rB = rA + 8;
        sfr[mt][0] = freq[rA]; sfr[mt][1] = freq[rB];
        sim[mt][0] = imp[rA];  sim[mt][1] = imp[rB];
    }

    float acc[4][4][4];
    #pragma unroll
    for (int mt = 0; mt < 4; mt++)
        #pragma unroll
        for (int nt = 0; nt < 4; nt++)
            #pragma unroll
            for (int q = 0; q < 4; q++) acc[mt][nt][q] = 0.f;

    const int nc = K / BK;
    #pragma unroll
    for (int i = 0; i < 4; i++) { cp16(adst[i], asrc[i], 16); cp16(bdst[i], bsrc[i], 16); }
    asm volatile("cp.async.commit_group;" ::: "memory");
    #pragma unroll
    for (int i = 0; i < 4; i++) { cp16(adst[i] + STGB, asrc[i] + BK, 16); cp16(bdst[i] + STGB, bsrc[i] + BK, 16); }
    asm volatile("cp.async.commit_group;" ::: "memory");

    for (int ch = 0; ch < nc; ch++) {
        asm volatile("cp.async.wait_group 1;" ::: "memory");
        __syncthreads();
        if (ch + 2 < nc) {
            const int koff = (ch + 2) * BK;
            const unsigned so = ((ch + 2) % 3) * STGB;
            #pragma unroll
            for (int i = 0; i < 4; i++) {
                cp16(adst[i] + so, asrc[i] + koff, 16);
                cp16(bdst[i] + so, bsrc[i] + koff, 16);
            }
        }
        asm volatile("cp.async.commit_group;" ::: "memory");

        const float* As = sm + (ch % 3) * STGW;
        const float* Bs = As + ASZ;
        const bool useFr = (ch * BK * 2 < K);

        #pragma unroll
        for (int ks = 0; ks < 4; ks++) {
            const int kb2 = ks * 2;
            unsigned afr[4][4];
            #pragma unroll
            for (int mt = 0; mt < 4; mt++) {
                int m = wm0 + mt * 16 + g;
                int sw = m & 7;
                int q0 = (kb2 ^ sw) * 4 + c;
                int q1 = ((kb2 + 1) ^ sw) * 4 + c;
                const float* pr0 = As + m * BK;
                const float* pr1 = As + (m + 8) * BK;
                float s0 = useFr ? sfr[mt][0] : sim[mt][0];
                float s1 = useFr ? sfr[mt][1] : sim[mt][1];
                afr[mt][0] = __float_as_uint(pr0[q0] * s0);
                afr[mt][1] = __float_as_uint(pr1[q0] * s1);
                afr[mt][2] = __float_as_uint(pr0[q1] * s0);
                afr[mt][3] = __float_as_uint(pr1[q1] * s1);
            }
            unsigned bfr[4][2];
            #pragma unroll
            for (int nt = 0; nt < 4; nt++) {
                int n = wn0 + nt * 8 + g;
                int sw = n & 7;
                const float* pn = Bs + n * BK;
                bfr[nt][0] = __float_as_uint(pn[(kb2 ^ sw) * 4 + c]);
                bfr[nt][1] = __float_as_uint(pn[((kb2 + 1) ^ sw) * 4 + c]);
            }
            #pragma unroll
            for (int mt = 0; mt < 4; mt++)
                #pragma unroll
                for (int nt = 0; nt < 4; nt++)
                    mma_tf32(acc[mt][nt], afr[mt], bfr[nt]);
        }
    }

    // Fused selector epilogue: partial logits for this n-tile.
    __syncthreads();
    float* part = sm;                // [warpN=4][128 rows][3]
    float w2v[3][8], bbv[8];
    #pragma unroll
    for (int nt = 0; nt < 4; nt++)
        #pragma unroll
        for (int cc = 0; cc < 2; cc++) {
            int col = tileN + wn0 + nt * 8 + c * 2 + cc;
            bbv[nt * 2 + cc]    = bias[col];
            w2v[0][nt * 2 + cc] = W2sel[col];
            w2v[1][nt * 2 + cc] = W2sel[512 + col];
            w2v[2][nt * 2 + cc] = W2sel[1024 + col];
        }
    #pragma unroll
    for (int mt = 0; mt < 4; mt++)
        #pragma unroll
        for (int h2 = 0; h2 < 2; h2++) {
            int r = wm0 + mt * 16 + g + 8 * h2;
            float l0 = 0.f, l1 = 0.f, l2 = 0.f;
            #pragma unroll
            for (int nt = 0; nt < 4; nt++)
                #pragma unroll
                for (int cc = 0; cc < 2; cc++) {
                    float v = fmaxf(acc[mt][nt][2 * h2 + cc] + bbv[nt * 2 + cc], 0.f);
                    l0 = fmaf(v, w2v[0][nt * 2 + cc], l0);
                    l1 = fmaf(v, w2v[1][nt * 2 + cc], l1);
                    l2 = fmaf(v, w2v[2][nt * 2 + cc], l2);
                }
            l0 += __shfl_down_sync(0xffffffffu, l0, 2, 4);
            l1 += __shfl_down_sync(0xffffffffu, l1, 2, 4);
            l2 += __shfl_down_sync(0xffffffffu, l2, 2, 4);
            l0 += __shfl_down_sync(0xffffffffu, l0, 1, 4);
            l1 += __shfl_down_sync(0xffffffffu, l1, 1, 4);
            l2 += __shfl_down_sync(0xffffffffu, l2, 1, 4);
            if (c == 0) {
                float* pr = part + ((size_t)(warp & 3) * 128 + r) * 3;
                pr[0] = l0; pr[1] = l1; pr[2] = l2;
            }
        }
    __syncthreads();
    if (tid < 128) {
        float s0 = 0.f, s1 = 0.f, s2 = 0.f;
        #pragma unroll
        for (int w = 0; w < 4; w++) {
            const float* pr = part + ((size_t)w * 128 + tid) * 3;
            s0 += pr[0]; s1 += pr[1]; s2 += pr[2];
        }
        float* dst = &g_psel[tileM + tid][blockIdx.x][0];
        dst[0] = s0; dst[1] = s1; dst[2] = s2;
    }
}

// ---------------------------------------------------------------------------
// Branch GEMM: 128x256 tile, warp tile 64x64 (1.0 LDS per mma vs 1.5 before,
// half the barriers per FLOP). Same K-order -> bit-identical results.
// ---------------------------------------------------------------------------
#define BSZ2  (256 * BK)                   // words for B per stage
#define STGW2 (ASZ + BSZ2)                 // words per stage
#define STGB2 (STGW2 * 4)                  // 49152 bytes
#define TC2_SMEM (3 * STGB2)               // 144 KB

struct Job {
    const float* A; const float* W; const float* bias; float* C;
    const int* cntp; int K; int N;
    const int* gather; const int* scatter; int ldc;
};

__global__ __launch_bounds__(256, 1)
void k_gemm_dual2(Job j0, Job j1)
{
    const Job& jb = (blockIdx.z == 0) ? j0 : j1;
    int M = *jb.cntp;
    const int tileM = blockIdx.y * 128;
    if (tileM >= M) return;
    const int tileN = blockIdx.x * 256;
    if (tileN >= jb.N) return;
    const int K = jb.K;

    extern __shared__ float sm[];

    const int tid  = threadIdx.x;
    const int lane = tid & 31;
    const int warp = tid >> 5;
    const int wm0 = (warp >> 2) * 64;      // 0..1 -> 0/64
    const int wn0 = (warp & 3) * 64;       // 0..3 -> 0/64/128/192
    const int g = lane >> 2;
    const int c = lane & 3;

    // Loaders: A 4 rows/thread, B 8 rows/thread (granule j of each row)
    const int j  = tid & 7;
    const int r0 = tid >> 3;               // 0..31
    const float* asrc[4]; int asz[4];
    const float* bsrc[8];
    unsigned adst[4], bdst[8];
    const unsigned smb = (unsigned)__cvta_generic_to_shared(sm);
    #pragma unroll
    for (int i = 0; i < 4; i++) {
        int r = r0 + 32 * i;
        int m = tileM + r;
        bool v = (m < M);
        int grow = v ? (jb.gather ? jb.gather[m] : m) : 0;
        asrc[i] = jb.A + (size_t)grow * K + j * 4;
        asz[i]  = v ? 16 : 0;
        unsigned woff = r * BK + ((j ^ (r & 7)) << 2);
        adst[i] = smb + woff * 4;
    }
    #pragma unroll
    for (int i = 0; i < 8; i++) {
        int r = r0 + 32 * i;               // 0..255
        bsrc[i] = jb.W + (size_t)(tileN + r) * K + j * 4;
        unsigned woff = r * BK + ((j ^ (r & 7)) << 2);
        bdst[i] = smb + (ASZ + woff) * 4;
    }

    float acc[4][8][4];
    #pragma unroll
    for (int mt = 0; mt < 4; mt++)
        #pragma unroll
        for (int nt = 0; nt < 8; nt++)
            #pragma unroll
            for (int q = 0; q < 4; q++) acc[mt][nt][q] = 0.f;

    const int nc = K / BK;
    #pragma unroll
    for (int i = 0; i < 4; i++) cp16(adst[i], asrc[i], asz[i]);
    #pragma unroll
    for (int i = 0; i < 8; i++) cp16(bdst[i], bsrc[i], 16);
    asm volatile("cp.async.commit_group;" ::: "memory");
    if (nc > 1) {
        #pragma unroll
        for (int i = 0; i < 4; i++) cp16(adst[i] + STGB2, asrc[i] + BK, asz[i]);
        #pragma unroll
        for (int i = 0; i < 8; i++) cp16(bdst[i] + STGB2, bsrc[i] + BK, 16);
    }
    asm volatile("cp.async.commit_group;" ::: "memory");

    for (int ch = 0; ch < nc; ch++) {
        asm volatile("cp.async.wait_group 1;" ::: "memory");
        __syncthreads();
        if (ch + 2 < nc) {
            const int koff = (ch + 2) * BK;
            const unsigned so = ((ch + 2) % 3) * STGB2;
            #pragma unroll
            for (int i = 0; i < 4; i++) cp16(adst[i] + so, asrc[i] + koff, asz[i]);
            #pragma unroll
            for (int i = 0; i < 8; i++) cp16(bdst[i] + so, bsrc[i] + koff, 16);
        }
        asm volatile("cp.async.commit_group;" ::: "memory");

        const float* As = sm + (ch % 3) * STGW2;
        const float* Bs = As + ASZ;

        #pragma unroll
        for (int ks = 0; ks < 4; ks++) {
            const int kb2 = ks * 2;
            unsigned afr[4][4];
            #pragma unroll
            for (int mt = 0; mt < 4; mt++) {
                int m = wm0 + mt * 16 + g;
                int sw = m & 7;
                int q0 = (kb2 ^ sw) * 4 + c;
                int q1 = ((kb2 + 1) ^ sw) * 4 + c;
                const float* pr0 = As + m * BK;
                const float* pr1 = As + (m + 8) * BK;
                afr[mt][0] = __float_as_uint(pr0[q0]);
                afr[mt][1] = __float_as_uint(pr1[q0]);
                afr[mt][2] = __float_as_uint(pr0[q1]);
                afr[mt][3] = __float_as_uint(pr1[q1]);
            }
            unsigned bfr[8][2];
            #pragma unroll
            for (int nt = 0; nt < 8; nt++) {
                int n = wn0 + nt * 8 + g;
                int sw = n & 7;
                const float* pn = Bs + n * BK;
                bfr[nt][0] = __float_as_uint(pn[(kb2 ^ sw) * 4 + c]);
                bfr[nt][1] = __float_as_uint(pn[((kb2 + 1) ^ sw) * 4 + c]);
            }
            #pragma unroll
            for (int mt = 0; mt < 4; mt++)
                #pragma unroll
                for (int nt = 0; nt < 8; nt++)
                    mma_tf32(acc[mt][nt], afr[mt], bfr[nt]);
        }
    }

    // Epilogue: bias + optional row scatter. float2 stores.
    #pragma unroll
    for (int mt = 0; mt < 4; mt++) {
        int rowA = tileM + wm0 + mt * 16 + g;
        #pragma unroll
        for (int h2 = 0; h2 < 2; h2++) {
            int r = rowA + 8 * h2;
            if (r >= M) continue;
            int cr = jb.scatter ? jb.scatter[r] : r;
            float* crow = jb.C + (size_t)cr * jb.ldc;
            #pragma unroll
            for (int nt = 0; nt < 8; nt++) {
                int col = tileN + wn0 + nt * 8 + c * 2;
                float2 bb = *(const float2*)(jb.bias + col);
                float2 o;
                o.x = acc[mt][nt][2 * h2 + 0] + bb.x;
                o.y = acc[mt][nt][2 * h2 + 1] + bb.y;
                *(float2*)(crow + col) = o;
            }
        }
    }
}

// ---------------------------------------------------------------------------
extern "C" void kernel_launch(void* const* d_in, const int* in_sizes, int n_in,
                              void* d_out, int out_size)
{
    const float* h       = (const float*)d_in[0];   // [4,4096,2048]
    const float* freq    = (const float*)d_in[1];   // [4,4096]
    const float* imp     = (const float*)d_in[2];   // [4,4096]
    const float* comp1_W = (const float*)d_in[3];   // [1024,2048]
    const float* comp1_b = (const float*)d_in[4];
    const float* adpt1_W = (const float*)d_in[5];   // [1024,1024]
    const float* adpt1_b = (const float*)d_in[6];
    const float* dec1_W  = (const float*)d_in[7];   // [2048,1024]
    const float* dec1_b  = (const float*)d_in[8];
    const float* comp2_W = (const float*)d_in[9];   // [512,2048]
    const float* comp2_b = (const float*)d_in[10];
    const float* adpt2_W = (const float*)d_in[11];  // [512,512]
    const float* adpt2_b = (const float*)d_in[12];
    const float* dec2_W  = (const float*)d_in[13];  // [2048,512]
    const float* dec2_b  = (const float*)d_in[14];
    const float* sel1_W  = (const float*)d_in[15];  // [512,2048]
    const float* sel1_b  = (const float*)d_in[16];
    const float* sel2_W  = (const float*)d_in[17];  // [3,512]
    const float* sel2_b  = (const float*)d_in[18];
    float* out = (float*)d_out;

    float *bufA, *bufB, *bufC, *bufD; int *idx1, *idx2, *cnt;
    cudaGetSymbolAddress((void**)&bufA, g_bufA);
    cudaGetSymbolAddress((void**)&bufB, g_bufB);
    cudaGetSymbolAddress((void**)&bufC, g_bufC);
    cudaGetSymbolAddress((void**)&bufD, g_bufD);
    cudaGetSymbolAddress((void**)&idx1, g_idx1);
    cudaGetSymbolAddress((void**)&idx2, g_idx2);
    cudaGetSymbolAddress((void**)&cnt,  g_cnt);

    cudaFuncSetAttribute(k_gemm_sel,
        cudaFuncAttributeMaxDynamicSharedMemorySize, TC_SMEM);
    cudaFuncSetAttribute(k_gemm_dual2,
        cudaFuncAttributeMaxDynamicSharedMemorySize, TC2_SMEM);

    const int MAXY = TOK / 128;  // 128 m-tiles

    // out = h ; counters zeroed by block 0
    {
        int n4 = TOK * HDIM / 4;
        k_prep<<<(n4 + 255) / 256, 256>>>(h, out);
    }

    // selector: tensor-core GEMM with fused tier-1 logit partials
    k_gemm_sel<<<dim3(512 / 128, MAXY), 256, TC_SMEM>>>(
        h, sel1_W, sel1_b, freq, imp, sel2_W);

    // tier-1 decision + near-tie flagging (fixed-order partial combine)
    k_seldec<<<TOK / 256, 256>>>(sel2_b);

    // tier-2: exact fp32 recheck, RQ-way jcol split
    k_sel_exact<<<dim3(148, RQ), 256>>>(h, freq, imp, sel1_W, sel1_b, sel2_W);

    // final decisions (inline recheck combine) + branch index lists
    k_compact<<<(TOK + 255) / 256, 256>>>(sel2_b);

    // ---- both branches, pairwise-merged 128x256 GEMMs (z = branch) ----
    {   // compress: b1 h->bufB [n1,1024] ; b2 h->bufC [n2,512]
        Job j0 = {h, comp1_W, comp1_b, bufB, &cnt[0], HDIM, 1024, idx1, nullptr, 1024};
        Job j1 = {h, comp2_W, comp2_b, bufC, &cnt[1], HDIM,  512, idx2, nullptr,  512};
        k_gemm_dual2<<<dim3(4, MAXY, 2), 256, TC2_SMEM>>>(j0, j1);
    }
    {   // adapt: b1 bufB->bufA ; b2 bufC->bufD
        Job j0 = {bufB, adpt1_W, adpt1_b, bufA, &cnt[0], 1024, 1024, nullptr, nullptr, 1024};
        Job j1 = {bufC, adpt2_W, adpt2_b, bufD, &cnt[1],  512,  512, nullptr, nullptr,  512};
        k_gemm_dual2<<<dim3(4, MAXY, 2), 256, TC2_SMEM>>>(j0, j1);
    }
    {   // decompress + scatter into out
        Job j0 = {bufA, dec1_W, dec1_b, out, &cnt[0], 1024, HDIM, nullptr, idx1, HDIM};
        Job j1 = {bufD, dec2_W, dec2_b, out, &cnt[1],  512, HDIM, nullptr, idx2, HDIM};
        k_gemm_dual2<<<dim3(8, MAXY, 2), 256, TC2_SMEM>>>(j0, j1);
    }
}

// round 15
// speedup vs baseline: 1.0251x; 1.0251x over previous
#include <cuda_runtime.h>

// Problem constants (fixed shapes from reference)
#define TOK   (4 * 4096)   // B*S = 16384 tokens
#define HDIM  2048
#define TAU   3e-3f        // tier-1 argmax-gap threshold (tf32 fast pass)
#define RTB   4            // tokens batched per recheck block
#define RQ    8            // recheck jcol split factor

// Scratch
__device__ float g_bufA[(size_t)TOK * 1024];  // branch1 stage-2
__device__ float g_bufB[(size_t)TOK * 1024];  // branch1 stage-1
__device__ float g_bufC[(size_t)TOK * 512];   // branch2 stage-1
__device__ float g_bufD[(size_t)TOK * 512];   // branch2 stage-2
__device__ float g_psel[TOK][4][3];           // fused tier-1 logit partials
__device__ float g_rpart[TOK][RQ][3];         // recheck partial logits
__device__ int   g_idx0[TOK];
__device__ int   g_idx1[TOK];
__device__ int   g_idx2[TOK];
__device__ int   g_idxR[TOK];
__device__ int   g_rIdx[TOK];                 // per-token recheck slot (-1 = none)
__device__ int   g_sel[TOK];
__device__ int   g_cnt[4];   // [0]=branch1, [1]=branch2, [2]=recheck, [3]=sel0

// ---------------------------------------------------------------------------
__global__ void k_init() {
    if (threadIdx.x < 4) g_cnt[threadIdx.x] = 0;
}

// ---------------------------------------------------------------------------
// Tier-1 decision from fused selector partials (fixed combine order).
// Near-ties (gap < TAU) get a recheck slot recorded in g_rIdx.
__global__ void k_seldec(const float* __restrict__ b2) {
    int tok = blockIdx.x * blockDim.x + threadIdx.x;
    if (tok >= TOK) return;
    float s0 = b2[0], s1 = b2[1], s2 = b2[2];
    #pragma unroll
    for (int q = 0; q < 4; q++) {
        s0 += g_psel[tok][q][0];
        s1 += g_psel[tok][q][1];
        s2 += g_psel[tok][q][2];
    }
    int sel = 0; float best = s0;             // first-max rule: strict '>'
    if (s1 > best) { best = s1; sel = 1; }
    if (s2 > best) { best = s2; sel = 2; }
    g_sel[tok] = sel;
    float m1 = fmaxf(s0, fmaxf(s1, s2));
    float mn = fminf(s0, fminf(s1, s2));
    float m2 = s0 + s1 + s2 - m1 - mn;        // second largest
    int flag = -1;
    if (m1 - m2 < TAU) {
        int p = atomicAdd(&g_cnt[2], 1);
        g_idxR[p] = tok;
        flag = p;
    }
    g_rIdx[tok] = flag;
}

// Tier-2: exact fp32 recompute, RTB tokens per block, jcols split RQ ways
// across blockIdx.y. Coalesced W1 loads; fixed-order reduces throughout.
__global__ __launch_bounds__(256)
void k_sel_exact(const float* __restrict__ h,
                 const float* __restrict__ freq,
                 const float* __restrict__ imp,
                 const float* __restrict__ W1,   // [512,2048]
                 const float* __restrict__ b1,
                 const float* __restrict__ W2)   // [3,512]
{
    __shared__ float xs[RTB][HDIM];          // 32 KB
    __shared__ float wp[8][RTB][3];          // per-warp logit partials
    const int tid  = threadIdx.x;
    const int lane = tid & 31;
    const int warp = tid >> 5;
    const int qy   = blockIdx.y;             // jcol slice 0..RQ-1
    const int nR = g_cnt[2];
    for (int base = blockIdx.x * RTB; base < nR; base += gridDim.x * RTB) {
        const int nt = min(RTB, nR - base);
        __syncthreads();                     // protect xs/wp reuse across iters
        for (int t = 0; t < nt; t++) {
            int tok = g_idxR[base + t];
            float fr = freq[tok], im = imp[tok];
            for (int k = tid; k < HDIM; k += 256) {
                float s = (k < HDIM / 2) ? fr : im;
                xs[t][k] = h[(size_t)tok * HDIM + k] * s;
            }
        }
        for (int t = nt; t < RTB; t++)
            for (int k = tid; k < HDIM; k += 256) xs[t][k] = 0.f;
        __syncthreads();

        float p[RTB][3];
        #pragma unroll
        for (int t = 0; t < RTB; t++)
            p[t][0] = p[t][1] = p[t][2] = 0.f;

        // this block: jcols [qy*64, qy*64+64); warp handles 8, 4 at a time
        #pragma unroll
        for (int grp = 0; grp < 2; grp++) {
            const int jcol0 = qy * 64 + warp * 8 + grp * 4;
            const float4* w0 = (const float4*)(W1 + (size_t)(jcol0 + 0) * HDIM);
            const float4* w1 = (const float4*)(W1 + (size_t)(jcol0 + 1) * HDIM);
            const float4* w2 = (const float4*)(W1 + (size_t)(jcol0 + 2) * HDIM);
            const float4* w3 = (const float4*)(W1 + (size_t)(jcol0 + 3) * HDIM);
            float acc[4][RTB];
            #pragma unroll
            for (int jj = 0; jj < 4; jj++)
                #pragma unroll
                for (int t = 0; t < RTB; t++) acc[jj][t] = 0.f;

            #pragma unroll 2
            for (int q = 0; q < 16; q++) {
                const int k4 = lane + q * 32;          // coalesced
                float4 wv[4] = {w0[k4], w1[k4], w2[k4], w3[k4]};
                float4 xv[RTB];
                #pragma unroll
                for (int t = 0; t < RTB; t++)
                    xv[t] = ((const float4*)xs[t])[k4];
                #pragma unroll
                for (int jj = 0; jj < 4; jj++)
                    #pragma unroll
                    for (int t = 0; t < RTB; t++)
                        acc[jj][t] = fmaf(wv[jj].x, xv[t].x,
                                     fmaf(wv[jj].y, xv[t].y,
                                     fmaf(wv[jj].z, xv[t].z,
                                     fmaf(wv[jj].w, xv[t].w, acc[jj][t]))));
            }
            // fixed shfl tree reduce
            #pragma unroll
            for (int o = 16; o; o >>= 1)
                #pragma unroll
                for (int jj = 0; jj < 4; jj++)
                    #pragma unroll
                    for (int t = 0; t < RTB; t++)
                        acc[jj][t] += __shfl_down_sync(0xffffffffu, acc[jj][t], o);
            if (lane == 0) {
                #pragma unroll
                for (int jj = 0; jj < 4; jj++) {
                    const int jcol = jcol0 + jj;
                    float bb  = b1[jcol];
                    float w20 = W2[jcol], w21 = W2[512 + jcol], w22 = W2[1024 + jcol];
                    #pragma unroll
                    for (int t = 0; t < RTB; t++) {
                        float hj = fmaxf(acc[jj][t] + bb, 0.f);
                        p[t][0] = fmaf(hj, w20, p[t][0]);
                        p[t][1] = fmaf(hj, w21, p[t][1]);
                        p[t][2] = fmaf(hj, w22, p[t][2]);
                    }
                }
            }
        }

        if (lane == 0)
            #pragma unroll
            for (int t = 0; t < RTB; t++) {
                wp[warp][t][0] = p[t][0];
                wp[warp][t][1] = p[t][1];
                wp[warp][t][2] = p[t][2];
            }
        __syncthreads();
        if (tid < nt) {
            float s0 = 0.f, s1 = 0.f, s2 = 0.f;
            #pragma unroll
            for (int w = 0; w < 8; w++) {
                s0 += wp[w][tid][0];
                s1 += wp[w][tid][1];
                s2 += wp[w][tid][2];
            }
            g_rpart[base + tid][qy][0] = s0;
            g_rpart[base + tid][qy][1] = s1;
            g_rpart[base + tid][qy][2] = s2;
        }
    }
}

// Build all three index lists. Rechecked tokens combine their RQ partials in
// fixed order (exact fp32 decision); others use the tier-1 decision.
__global__ void k_compact(const float* __restrict__ b2) {
    int tok = blockIdx.x * blockDim.x + threadIdx.x;
    if (tok >= TOK) return;
    int r = g_rIdx[tok];
    int sel;
    if (r >= 0) {
        float s0 = b2[0], s1 = b2[1], s2 = b2[2];
        #pragma unroll
        for (int q = 0; q < RQ; q++) {
            s0 += g_rpart[r][q][0];
            s1 += g_rpart[r][q][1];
            s2 += g_rpart[r][q][2];
        }
        sel = 0; float best = s0;
        if (s1 > best) { best = s1; sel = 1; }
        if (s2 > best) { best = s2; sel = 2; }
    } else {
        sel = g_sel[tok];
    }
    if (sel == 1)      { int p = atomicAdd(&g_cnt[0], 1); g_idx1[p] = tok; }
    else if (sel == 2) { int p = atomicAdd(&g_cnt[1], 1); g_idx2[p] = tok; }
    else               { int p = atomicAdd(&g_cnt[3], 1); g_idx0[p] = tok; }
}

// Deferred copy: out rows for sel==0 tokens only (branches overwrite theirs).
__global__ void k_copy0(const float* __restrict__ h, float* __restrict__ out) {
    int i = blockIdx.x * blockDim.x + threadIdx.x;   // float4 slot
    int slot = i >> 9;                               // 512 float4 per row
    if (slot >= g_cnt[3]) return;
    int tok = g_idx0[slot];
    int col4 = i & 511;
    ((float4*)out)[(size_t)tok * 512 + col4] =
        ((const float4*)h)[(size_t)tok * 512 + col4];
}

// ---------------------------------------------------------------------------
// tf32 tensor-core GEMM machinery (mma.m16n8k8, cp.async 3-stage, XOR swizzle)
// ---------------------------------------------------------------------------
__device__ __forceinline__ void mma_tf32(float (&d)[4], const unsigned (&a)[4],
                                         const unsigned (&b)[2]) {
    asm volatile(
        "mma.sync.aligned.m16n8k8.row.col.f32.tf32.tf32.f32 "
        "{%0,%1,%2,%3}, {%4,%5,%6,%7}, {%8,%9}, {%0,%1,%2,%3};\n"
        : "+f"(d[0]), "+f"(d[1]), "+f"(d[2]), "+f"(d[3])
        : "r"(a[0]), "r"(a[1]), "r"(a[2]), "r"(a[3]), "r"(b[0]), "r"(b[1]));
}

__device__ __forceinline__ void cp16(unsigned dst, const void* src, int nbytes) {
    asm volatile("cp.async.cg.shared.global [%0], [%1], 16, %2;"
                 :: "r"(dst), "l"(src), "r"(nbytes));
}

#define BK   32
#define ASZ  (128 * BK)                    // words per matrix per stage
#define STGW (2 * ASZ)                     // words per stage (A+B)
#define STGB (STGW * 4)                    // bytes per stage
#define TC_SMEM (3 * STGB)                 // 96 KB

template<bool MOD>
__device__ __forceinline__ void gemm_tc_body(
    const float* __restrict__ A, const float* __restrict__ W,
    const float* __restrict__ bias, float* __restrict__ C,
    int M, int K, const int* __restrict__ gather,
    const int* __restrict__ scatter, int ldc, int relu,
    const float* __restrict__ freq, const float* __restrict__ imp,
    const float* __restrict__ W2sel, float* __restrict__ psel,
    int tileM, int tileN)
{
    extern __shared__ float sm[];

    const int tid  = threadIdx.x;
    const int lane = tid & 31;
    const int warp = tid >> 5;
    const int wm0 = (warp >> 2) * 64;
    const int wn0 = (warp & 3) * 32;
    const int g = lane >> 2;           // 0..7
    const int c = lane & 3;            // 0..3

    // Loader mapping: granule j (16B) within row, 4 rows per thread per matrix.
    const int j  = tid & 7;
    const int r0 = tid >> 3;           // 0..31
    const float* asrc[4]; int asz[4];
    const float* bsrc[4];
    unsigned adst[4], bdst[4];
    const unsigned smb = (unsigned)__cvta_generic_to_shared(sm);
    #pragma unroll
    for (int i = 0; i < 4; i++) {
        int r = r0 + 32 * i;           // tile row 0..127
        int m = tileM + r;
        bool v = (m < M);
        int grow = v ? (gather ? gather[m] : m) : 0;
        asrc[i] = A + (size_t)grow * K + j * 4;
        asz[i]  = v ? 16 : 0;          // zfill invalid rows
        bsrc[i] = W + (size_t)(tileN + r) * K + j * 4;
        unsigned woff = r * BK + ((j ^ (r & 7)) << 2);
        adst[i] = smb + woff * 4;
        bdst[i] = smb + (ASZ + woff) * 4;
    }

    // Per-row modulation scales (selector path only; M = TOK, rows in-range).
    float sfr[4][2], sim[4][2];
    if (MOD) {
        #pragma unroll
        for (int mt = 0; mt < 4; mt++) {
            int rA = tileM + wm0 + mt * 16 + g;
            int rB = rA + 8;
            sfr[mt][0] = freq[rA]; sfr[mt][1] = freq[rB];
            sim[mt][0] = imp[rA];  sim[mt][1] = imp[rB];
        }
    }

    float acc[4][4][4];
    #pragma unroll
    for (int mt = 0; mt < 4; mt++)
        #pragma unroll
        for (int nt = 0; nt < 4; nt++)
            #pragma unroll
            for (int q = 0; q < 4; q++) acc[mt][nt][q] = 0.f;

    const int nc = K / BK;

    // Preload stages 0 and 1 (two committed groups)
    #pragma unroll
    for (int i = 0; i < 4; i++) {
        cp16(adst[i], asrc[i], asz[i]);
        cp16(bdst[i], bsrc[i], 16);
    }
    asm volatile("cp.async.commit_group;" ::: "memory");
    if (nc > 1) {
        #pragma unroll
        for (int i = 0; i < 4; i++) {
            cp16(adst[i] + STGB, asrc[i] + BK, asz[i]);
            cp16(bdst[i] + STGB, bsrc[i] + BK, 16);
        }
    }
    asm volatile("cp.async.commit_group;" ::: "memory");

    for (int ch = 0; ch < nc; ch++) {
        asm volatile("cp.async.wait_group 1;" ::: "memory");
        __syncthreads();

        if (ch + 2 < nc) {
            const int koff = (ch + 2) * BK;
            const unsigned so = ((ch + 2) % 3) * STGB;
            #pragma unroll
            for (int i = 0; i < 4; i++) {
                cp16(adst[i] + so, asrc[i] + koff, asz[i]);
                cp16(bdst[i] + so, bsrc[i] + koff, 16);
            }
        }
        asm volatile("cp.async.commit_group;" ::: "memory");

        const float* As = sm + (ch % 3) * STGW;
        const float* Bs = As + ASZ;
        const bool useFr = MOD && (ch * BK * 2 < K);   // first half of K

        #pragma unroll
        for (int ks = 0; ks < 4; ks++) {
            const int kb2 = ks * 2;            // granule index pair base
            unsigned afr[4][4];
            #pragma unroll
            for (int mt = 0; mt < 4; mt++) {
                int m = wm0 + mt * 16 + g;
                int sw = m & 7;                 // (m+8)&7 == m&7
                int q0 = (kb2 ^ sw) * 4 + c;
                int q1 = ((kb2 + 1) ^ sw) * 4 + c;
                const float* pr0 = As + m * BK;
                const float* pr1 = As + (m + 8) * BK;
                if (MOD) {
                    float s0 = useFr ? sfr[mt][0] : sim[mt][0];
                    float s1 = useFr ? sfr[mt][1] : sim[mt][1];
                    afr[mt][0] = __float_as_uint(pr0[q0] * s0);
                    afr[mt][1] = __float_as_uint(pr1[q0] * s1);
                    afr[mt][2] = __float_as_uint(pr0[q1] * s0);
                    afr[mt][3] = __float_as_uint(pr1[q1] * s1);
                } else {
                    afr[mt][0] = __float_as_uint(pr0[q0]);
                    afr[mt][1] = __float_as_uint(pr1[q0]);
                    afr[mt][2] = __float_as_uint(pr0[q1]);
                    afr[mt][3] = __float_as_uint(pr1[q1]);
                }
            }
            unsigned bfr[4][2];
            #pragma unroll
            for (int nt = 0; nt < 4; nt++) {
                int n = wn0 + nt * 8 + g;
                int sw = n & 7;
                const float* pn = Bs + n * BK;
                bfr[nt][0] = __float_as_uint(pn[(kb2 ^ sw) * 4 + c]);
                bfr[nt][1] = __float_as_uint(pn[((kb2 + 1) ^ sw) * 4 + c]);
            }
            #pragma unroll
            for (int mt = 0; mt < 4; mt++)
                #pragma unroll
                for (int nt = 0; nt < 4; nt++)
                    mma_tf32(acc[mt][nt], afr[mt], bfr[nt]);
        }
    }

    if (MOD) {
        // Fused selector epilogue: partial logits for this n-tile.
        __syncthreads();                 // smem free for reuse
        float* part = sm;                // [warpN=4][128 rows][3]
        float w2v[3][8], bbv[8];
        #pragma unroll
        for (int nt = 0; nt < 4; nt++)
            #pragma unroll
            for (int cc = 0; cc < 2; cc++) {
                int col = tileN + wn0 + nt * 8 + c * 2 + cc;
                bbv[nt * 2 + cc]    = bias[col];
                w2v[0][nt * 2 + cc] = W2sel[col];
                w2v[1][nt * 2 + cc] = W2sel[512 + col];
                w2v[2][nt * 2 + cc] = W2sel[1024 + col];
            }
        #pragma unroll
        for (int mt = 0; mt < 4; mt++)
            #pragma unroll
            for (int h2 = 0; h2 < 2; h2++) {
                int r = wm0 + mt * 16 + g + 8 * h2;
                float l0 = 0.f, l1 = 0.f, l2 = 0.f;
                #pragma unroll
                for (int nt = 0; nt < 4; nt++)
                    #pragma unroll
                    for (int cc = 0; cc < 2; cc++) {
                        float v = fmaxf(acc[mt][nt][2 * h2 + cc] + bbv[nt * 2 + cc], 0.f);
                        l0 = fmaf(v, w2v[0][nt * 2 + cc], l0);
                        l1 = fmaf(v, w2v[1][nt * 2 + cc], l1);
                        l2 = fmaf(v, w2v[2][nt * 2 + cc], l2);
                    }
                l0 += __shfl_down_sync(0xffffffffu, l0, 2, 4);
                l1 += __shfl_down_sync(0xffffffffu, l1, 2, 4);
                l2 += __shfl_down_sync(0xffffffffu, l2, 2, 4);
                l0 += __shfl_down_sync(0xffffffffu, l0, 1, 4);
                l1 += __shfl_down_sync(0xffffffffu, l1, 1, 4);
                l2 += __shfl_down_sync(0xffffffffu, l2, 1, 4);
                if (c == 0) {
                    float* pr = part + ((size_t)(warp & 3) * 128 + r) * 3;
                    pr[0] = l0; pr[1] = l1; pr[2] = l2;
                }
            }
        __syncthreads();
        if (tid < 128) {
            float s0 = 0.f, s1 = 0.f, s2 = 0.f;
            #pragma unroll
            for (int w = 0; w < 4; w++) {   // fixed order over warpN
                const float* pr = part + ((size_t)w * 128 + tid) * 3;
                s0 += pr[0]; s1 += pr[1]; s2 += pr[2];
            }
            float* dst = psel + ((size_t)(tileM + tid) * 4 + blockIdx.x) * 3;
            dst[0] = s0; dst[1] = s1; dst[2] = s2;
        }
        return;
    }

    // Epilogue: bias + optional row scatter. float2 stores.
    #pragma unroll
    for (int mt = 0; mt < 4; mt++) {
        int rowA = tileM + wm0 + mt * 16 + g;
        #pragma unroll
        for (int h2 = 0; h2 < 2; h2++) {
            int r = rowA + 8 * h2;
            if (r >= M) continue;
            int cr = scatter ? scatter[r] : r;
            float* crow = C + (size_t)cr * ldc;
            #pragma unroll
            for (int nt = 0; nt < 4; nt++) {
                int col = tileN + wn0 + nt * 8 + c * 2;
                float2 bb = *(const float2*)(bias + col);
                float2 o;
                o.x = acc[mt][nt][2 * h2 + 0] + bb.x;
                o.y = acc[mt][nt][2 * h2 + 1] + bb.y;
                if (relu) { o.x = fmaxf(o.x, 0.f); o.y = fmaxf(o.y, 0.f); }
                *(float2*)(crow + col) = o;
            }
        }
    }
}

// Selector GEMM: modulation + fused logit partials. Static M = TOK.
__global__ __launch_bounds__(256, 2)
void k_gemm_sel(const float* __restrict__ A, const float* __restrict__ W,
                const float* __restrict__ bias,
                const float* __restrict__ freq, const float* __restrict__ imp,
                const float* __restrict__ W2)
{
    gemm_tc_body<true>(A, W, bias, nullptr, TOK, HDIM, nullptr, nullptr, 0, 1,
                       freq, imp, W2, &g_psel[0][0][0],
                       blockIdx.y * 128, blockIdx.x * 128);
}

// Dual-branch GEMM: blockIdx.z selects the job (branch1 / branch2).
struct Job {
    const float* A; const float* W; const float* bias; float* C;
    const int* cntp; int K; int N;
    const int* gather; const int* scatter; int ldc;
};

__global__ __launch_bounds__(256, 2)
void k_gemm_dual(Job j0, Job j1)
{
    const Job& j = (blockIdx.z == 0) ? j0 : j1;
    int M = *j.cntp;
    int tileM = blockIdx.y * 128;
    if (tileM >= M) return;
    int tileN = blockIdx.x * 128;
    if (tileN >= j.N) return;
    gemm_tc_body<false>(j.A, j.W, j.bias, j.C, M, j.K, j.gather, j.scatter,
                        j.ldc, 0, nullptr, nullptr, nullptr, nullptr,
                        tileM, tileN);
}

// ---------------------------------------------------------------------------
extern "C" void kernel_launch(void* const* d_in, const int* in_sizes, int n_in,
                              void* d_out, int out_size)
{
    const float* h       = (const float*)d_in[0];   // [4,4096,2048]
    const float* freq    = (const float*)d_in[1];   // [4,4096]
    const float* imp     = (const float*)d_in[2];   // [4,4096]
    const float* comp1_W = (const float*)d_in[3];   // [1024,2048]
    const float* comp1_b = (const float*)d_in[4];
    const float* adpt1_W = (const float*)d_in[5];   // [1024,1024]
    const float* adpt1_b = (const float*)d_in[6];
    const float* dec1_W  = (const float*)d_in[7];   // [2048,1024]
    const float* dec1_b  = (const float*)d_in[8];
    const float* comp2_W = (const float*)d_in[9];   // [512,2048]
    const float* comp2_b = (const float*)d_in[10];
    const float* adpt2_W = (const float*)d_in[11];  // [512,512]
    const float* adpt2_b = (const float*)d_in[12];
    const float* dec2_W  = (const float*)d_in[13];  // [2048,512]
    const float* dec2_b  = (const float*)d_in[14];
    const float* sel1_W  = (const float*)d_in[15];  // [512,2048]
    const float* sel1_b  = (const float*)d_in[16];
    const float* sel2_W  = (const float*)d_in[17];  // [3,512]
    const float* sel2_b  = (const float*)d_in[18];
    float* out = (float*)d_out;

    float *bufA, *bufB, *bufC, *bufD; int *idx1, *idx2, *cnt;
    cudaGetSymbolAddress((void**)&bufA, g_bufA);
    cudaGetSymbolAddress((void**)&bufB, g_bufB);
    cudaGetSymbolAddress((void**)&bufC, g_bufC);
    cudaGetSymbolAddress((void**)&bufD, g_bufD);
    cudaGetSymbolAddress((void**)&idx1, g_idx1);
    cudaGetSymbolAddress((void**)&idx2, g_idx2);
    cudaGetSymbolAddress((void**)&cnt,  g_cnt);

    cudaFuncSetAttribute(k_gemm_sel,
        cudaFuncAttributeMaxDynamicSharedMemorySize, TC_SMEM);
    cudaFuncSetAttribute(k_gemm_dual,
        cudaFuncAttributeMaxDynamicSharedMemorySize, TC_SMEM);

    const int MAXY = TOK / 128;  // 128 m-tiles

    // zero counters
    k_init<<<1, 32>>>();

    // selector: tensor-core GEMM with fused tier-1 logit partials
    k_gemm_sel<<<dim3(512 / 128, MAXY), 256, TC_SMEM>>>(
        h, sel1_W, sel1_b, freq, imp, sel2_W);

    // tier-1 decision + near-tie flagging (fixed-order partial combine)
    k_seldec<<<TOK / 256, 256>>>(sel2_b);

    // tier-2: exact fp32 recheck, RQ-way jcol split
    k_sel_exact<<<dim3(148, RQ), 256>>>(h, freq, imp, sel1_W, sel1_b, sel2_W);

    // final decisions (inline recheck combine) + all three index lists
    k_compact<<<(TOK + 255) / 256, 256>>>(sel2_b);

    // deferred copy: only sel==0 rows (branches overwrite their own rows)
    k_copy0<<<TOK * 2, 256>>>(h, out);

    // ---- both branches, pairwise-merged GEMMs (z = branch) ----
    {   // compress: b1 h->bufB [n1,1024] ; b2 h->bufC [n2,512]
        Job j0 = {h, comp1_W, comp1_b, bufB, &cnt[0], HDIM, 1024, idx1, nullptr, 1024};
        Job j1 = {h, comp2_W, comp2_b, bufC, &cnt[1], HDIM,  512, idx2, nullptr,  512};
        k_gemm_dual<<<dim3(8, MAXY, 2), 256, TC_SMEM>>>(j0, j1);
    }
    {   // adapt: b1 bufB->bufA ; b2 bufC->bufD
        Job j0 = {bufB, adpt1_W, adpt1_b, bufA, &cnt[0], 1024, 1024, nullptr, nullptr, 1024};
        Job j1 = {bufC, adpt2_W, adpt2_b, bufD, &cnt[1],  512,  512, nullptr, nullptr,  512};
        k_gemm_dual<<<dim3(8, MAXY, 2), 256, TC_SMEM>>>(j0, j1);
    }
    {   // decompress + scatter into out
        Job j0 = {bufA, dec1_W, dec1_b, out, &cnt[0], 1024, HDIM, nullptr, idx1, HDIM};
        Job j1 = {bufD, dec2_W, dec2_b, out, &cnt[1],  512, HDIM, nullptr, idx2, HDIM};
        k_gemm_dual<<<dim3(16, MAXY, 2), 256, TC_SMEM>>>(j0, j1);
    }
}